// round 5
// baseline (speedup 1.0000x reference)
#include <cuda_runtime.h>
#include <cuda_bf16.h>
#include <cstdint>

#define DI __device__ __forceinline__

// ---------------- constants ----------------
constexpr int DIM = 128;
constexpr int ROW_FLOATS = DIM * DIM;        // 16384 floats per sample
constexpr int ROW_BYTES = DIM * 2;           // 256 B per bf16 tile row
constexpr int TILE_BYTES = DIM * ROW_BYTES;  // 32 KB full tile
constexpr int NT = 512;                      // 8 compute + 8 producer warps

// SMEM map (224 KB total)
constexpr int OFF_WB_HI = 0;
constexpr int OFF_WB_LO = 1 * TILE_BYTES;
constexpr int OFF_WA_HI = 2 * TILE_BYTES;
constexpr int OFF_WA_LO = 3 * TILE_BYTES;
constexpr int OFF_U0    = 4 * TILE_BYTES;    // X hi  (refilled w/ next X hi)
constexpr int OFF_U1    = 5 * TILE_BYTES;    // X lo -> T lo -> next X lo
constexpr int OFF_V     = 6 * TILE_BYTES;    // T hi
constexpr int SMEM_BYTES = 7 * TILE_BYTES;   // 229376 B

// ---------------- helpers ----------------
DI uint32_t smem_u32(const void* p) {
    uint32_t a;
    asm("{ .reg .u64 t; cvta.to.shared.u64 t, %1; cvt.u32.u64 %0, t; }" : "=r"(a) : "l"(p));
    return a;
}

// Byte offset of (row, col[bf16]) in a swizzled 128x128 bf16 tile.
// Row = 256 B = 16 chunks of 16 B; chunk index XORed with (row & 7) so
// 8 consecutive rows hit 8 distinct bank groups (conflict-free ldmatrix).
DI uint32_t toff(int row, int col) {
    return (uint32_t)(row * ROW_BYTES) + ((((col >> 3) ^ (row & 7)) << 4)) +
           ((col & 7) << 1);
}

DI void ldsm4(uint32_t& r0, uint32_t& r1, uint32_t& r2, uint32_t& r3, uint32_t a) {
    asm volatile("ldmatrix.sync.aligned.m8n8.x4.shared.b16 {%0,%1,%2,%3}, [%4];"
                 : "=r"(r0), "=r"(r1), "=r"(r2), "=r"(r3) : "r"(a));
}

DI void mma16816(float* d, const uint32_t* a, uint32_t b0, uint32_t b1) {
    asm volatile(
        "mma.sync.aligned.m16n8k16.row.col.f32.bf16.bf16.f32 "
        "{%0,%1,%2,%3}, {%4,%5,%6,%7}, {%8,%9}, {%0,%1,%2,%3};"
        : "+f"(d[0]), "+f"(d[1]), "+f"(d[2]), "+f"(d[3])
        : "r"(a[0]), "r"(a[1]), "r"(a[2]), "r"(a[3]), "r"(b0), "r"(b1));
}

DI uint32_t prmt7632(uint32_t a, uint32_t b) {
    uint32_t r;
    asm("prmt.b32 %0, %1, %2, 0x7632;" : "=r"(r) : "r"(a), "r"(b));
    return r;
}

// Fast fp32 -> (hi bf16, lo bf16) split via truncation (3 ops/elem).
// hi = top 16 bits of f32; lo = bf16(a - hi). Total precision ~2^-14.
DI void fsplit2(float a, float b, uint32_t& h, uint32_t& l) {
    uint32_t ua = __float_as_uint(a), ub = __float_as_uint(b);
    h = prmt7632(ua, ub);
    float la = a - __uint_as_float(ua & 0xFFFF0000u);
    float lb = b - __uint_as_float(ub & 0xFFFF0000u);
    l = prmt7632(__float_as_uint(la), __float_as_uint(lb));
}

// Load 128x128 fp32 row-major from gmem, split, store swizzled hi/lo tiles.
DI void cvt_tile(const float* __restrict__ src, char* smem, int off_hi, int off_lo,
                 int tid) {
#pragma unroll
    for (int it = 0; it < 2048 / NT; it++) {
        int g = tid + it * NT;
        int row = g >> 4;
        int col = (g & 15) << 3;
        const float4* p = reinterpret_cast<const float4*>(src + row * DIM + col);
        float4 v0 = p[0];
        float4 v1 = p[1];
        uint4 hi, lo;
        fsplit2(v0.x, v0.y, hi.x, lo.x);
        fsplit2(v0.z, v0.w, hi.y, lo.y);
        fsplit2(v1.x, v1.y, hi.z, lo.z);
        fsplit2(v1.z, v1.w, hi.w, lo.w);
        uint32_t o = toff(row, col);
        *reinterpret_cast<uint4*>(smem + off_hi + o) = hi;
        *reinterpret_cast<uint4*>(smem + off_lo + o) = lo;
    }
}

// 128x128x128 fp32-accurate GEMM, warp tile m32 x n64.
// acc += Ah*Bh + Al*Bh + Ah*Bl  (lo*lo dropped).
DI void gemm3(float acc[2][8][4], uint32_t a_hi, uint32_t a_lo,
              uint32_t b_hi, uint32_t b_lo, int m0, int n0, int lane) {
    const int a_row = lane & 15;
    const int a_col = (lane >> 4) << 3;
    const int b_row = (lane & 7) + ((lane >> 4) << 3);
    const int b_col = ((lane >> 3) & 1) << 3;

#pragma unroll
    for (int k = 0; k < 8; k++) {
        const int kb = k << 4;
        uint32_t Ah[2][4], Al[2][4];
#pragma unroll
        for (int mt = 0; mt < 2; mt++) {
            uint32_t o = toff(m0 + mt * 16 + a_row, kb + a_col);
            ldsm4(Ah[mt][0], Ah[mt][1], Ah[mt][2], Ah[mt][3], a_hi + o);
            ldsm4(Al[mt][0], Al[mt][1], Al[mt][2], Al[mt][3], a_lo + o);
        }
#pragma unroll
        for (int p = 0; p < 4; p++) {
            uint32_t Bh[4], Bl[4];
            uint32_t o = toff(n0 + p * 16 + b_row, kb + b_col);
            ldsm4(Bh[0], Bh[1], Bh[2], Bh[3], b_hi + o);
            ldsm4(Bl[0], Bl[1], Bl[2], Bl[3], b_lo + o);
#pragma unroll
            for (int mt = 0; mt < 2; mt++) {
#pragma unroll
                for (int qn = 0; qn < 2; qn++) {
                    float* a4 = acc[mt][p * 2 + qn];
                    mma16816(a4, Ah[mt], Bh[qn * 2], Bh[qn * 2 + 1]);
                    mma16816(a4, Al[mt], Bh[qn * 2], Bh[qn * 2 + 1]);
                    mma16816(a4, Ah[mt], Bl[qn * 2], Bl[qn * 2 + 1]);
                }
            }
        }
    }
}

DI void zero_acc(float acc[2][8][4]) {
#pragma unroll
    for (int mt = 0; mt < 2; mt++)
#pragma unroll
        for (int nt = 0; nt < 8; nt++)
#pragma unroll
            for (int i = 0; i < 4; i++) acc[mt][nt][i] = 0.f;
}

// ---------------- kernel ----------------
__global__ void __launch_bounds__(NT, 1)
krone_kernel(const float* __restrict__ x, const float* __restrict__ wa,
             const float* __restrict__ wb, const float* __restrict__ bias,
             float* __restrict__ out, int n_samples) {
    extern __shared__ char smem[];
    const uint32_t sb = smem_u32(smem);
    const int tid = threadIdx.x;
    const int wid = tid >> 5;
    const int lane = tid & 31;
    const bool is_compute = wid < 8;
    const int m0 = (wid & 3) * 32;     // compute: output rows
    const int n0 = ((wid >> 2) & 1) * 64;  // compute: output cols
    const int tp = tid & 255;          // producer index 0..255

    // One-time: weights + first sample into smem (all 512 threads)
    cvt_tile(wb, smem, OFF_WB_HI, OFF_WB_LO, tid);
    cvt_tile(wa, smem, OFF_WA_HI, OFF_WA_LO, tid);
    {
        int n0s = blockIdx.x < n_samples ? blockIdx.x : 0;
        cvt_tile(x + (size_t)n0s * ROW_FLOATS, smem, OFF_U0, OFF_U1, tid);
    }
    __syncthreads();   // bar0: X(first) ready

    const int er = lane >> 2;
    const int ec = (lane & 3) << 1;

    float acc[2][8][4];
    uint32_t phx[8][4], plx[8][4];     // producer staging (next sample hi/lo)

    for (int n = blockIdx.x; n < n_samples; n += gridDim.x) {
        // ===== phase 1: GEMM1 | producer LDG+split next sample =====
        if (is_compute) {
            zero_acc(acc);
            gemm3(acc, sb + OFF_WB_HI, sb + OFF_WB_LO, sb + OFF_U0, sb + OFF_U1,
                  m0, n0, lane);
        } else {
            int np = n + gridDim.x;
            if (np >= n_samples) np = n;  // clamp (last iter: harmless reload)
            const float* src = x + (size_t)np * ROW_FLOATS;
#pragma unroll
            for (int it = 0; it < 8; it++) {
                int g = tp + (it << 8);
                int row = g >> 4;
                int col = (g & 15) << 3;
                const float4* p = reinterpret_cast<const float4*>(src + row * DIM + col);
                float4 v0 = p[0];
                float4 v1 = p[1];
                fsplit2(v0.x, v0.y, phx[it][0], plx[it][0]);
                fsplit2(v0.z, v0.w, phx[it][1], plx[it][1]);
                fsplit2(v1.x, v1.y, phx[it][2], plx[it][2]);
                fsplit2(v1.z, v1.w, phx[it][3], plx[it][3]);
            }
        }
        __syncthreads();   // bar1: GEMM1 done reading U0/U1

        // ===== phase 2: compute stores T (hi->V, lo->U1) | producer STS hi->U0
        if (is_compute) {
#pragma unroll
            for (int mt = 0; mt < 2; mt++) {
#pragma unroll
                for (int nt = 0; nt < 8; nt++) {
                    const int col = n0 + nt * 8 + ec;
                    uint32_t h, l;
                    fsplit2(acc[mt][nt][0], acc[mt][nt][1], h, l);
                    uint32_t o = toff(m0 + mt * 16 + er, col);
                    *reinterpret_cast<uint32_t*>(smem + OFF_V + o) = h;
                    *reinterpret_cast<uint32_t*>(smem + OFF_U1 + o) = l;
                    fsplit2(acc[mt][nt][2], acc[mt][nt][3], h, l);
                    o = toff(m0 + mt * 16 + er + 8, col);
                    *reinterpret_cast<uint32_t*>(smem + OFF_V + o) = h;
                    *reinterpret_cast<uint32_t*>(smem + OFF_U1 + o) = l;
                }
            }
        } else {
#pragma unroll
            for (int it = 0; it < 8; it++) {
                int g = tp + (it << 8);
                uint32_t o = toff(g >> 4, (g & 15) << 3);
                *reinterpret_cast<uint4*>(smem + OFF_U0 + o) =
                    *reinterpret_cast<uint4*>(phx[it]);
            }
        }
        __syncthreads();   // bar2: T ready

        // ===== phase 3: GEMM2 reads V (T hi) + U1 (T lo) =====
        if (is_compute) {
            zero_acc(acc);
            gemm3(acc, sb + OFF_WA_HI, sb + OFF_WA_LO, sb + OFF_V, sb + OFF_U1,
                  m0, n0, lane);
        }
        __syncthreads();   // bar3: GEMM2 done reading U1

        // ===== phase 4: epilogue | producer STS lo->U1 =====
        if (is_compute) {
            float* outn = out + (size_t)n * ROW_FLOATS;
#pragma unroll
            for (int mt = 0; mt < 2; mt++) {
#pragma unroll
                for (int nt = 0; nt < 8; nt++) {
                    const int col = n0 + nt * 8 + ec;
                    int row = m0 + mt * 16 + er;
                    float2 bv = *reinterpret_cast<const float2*>(bias + row * DIM + col);
                    float2 o0 = {acc[mt][nt][0] + bv.x, acc[mt][nt][1] + bv.y};
                    *reinterpret_cast<float2*>(outn + row * DIM + col) = o0;
                    row += 8;
                    bv = *reinterpret_cast<const float2*>(bias + row * DIM + col);
                    float2 o1 = {acc[mt][nt][2] + bv.x, acc[mt][nt][3] + bv.y};
                    *reinterpret_cast<float2*>(outn + row * DIM + col) = o1;
                }
            }
        } else {
#pragma unroll
            for (int it = 0; it < 8; it++) {
                int g = tp + (it << 8);
                uint32_t o = toff(g >> 4, (g & 15) << 3);
                *reinterpret_cast<uint4*>(smem + OFF_U1 + o) =
                    *reinterpret_cast<uint4*>(plx[it]);
            }
        }
        __syncthreads();   // bar0: next X fully staged in U0/U1
    }
}

// ---------------- launcher ----------------
extern "C" void kernel_launch(void* const* d_in, const int* in_sizes, int n_in,
                              void* d_out, int out_size) {
    const float* x    = (const float*)d_in[0];
    const float* wa   = (const float*)d_in[1];
    const float* wb   = (const float*)d_in[2];
    const float* bias = (const float*)d_in[3];
    float* out = (float*)d_out;
    int n_samples = in_sizes[0] / ROW_FLOATS;

    cudaFuncSetAttribute(krone_kernel, cudaFuncAttributeMaxDynamicSharedMemorySize,
                         SMEM_BYTES);
    int grid = n_samples < 148 ? n_samples : 148;
    krone_kernel<<<grid, NT, SMEM_BYTES>>>(x, wa, wb, bias, out, n_samples);
}

// round 7
// speedup vs baseline: 1.6901x; 1.6901x over previous
#include <cuda_runtime.h>
#include <cuda_fp16.h>
#include <cstdint>

#define DI __device__ __forceinline__

// ---------------- constants ----------------
constexpr int DIM = 128;
constexpr int ROW_FLOATS = DIM * DIM;        // 16384 floats per sample
constexpr int ROW_BYTES = DIM * 2;           // 256 B per fp16 tile row
constexpr int TILE_BYTES = DIM * ROW_BYTES;  // 32 KB
constexpr int NT = 512;                      // 16 warps, all compute

// SMEM map: 6 tiles = 192 KB
constexpr int OFF_WB_HI = 0;
constexpr int OFF_WB_LO = 1 * TILE_BYTES;
constexpr int OFF_WA_HI = 2 * TILE_BYTES;
constexpr int OFF_WA_LO = 3 * TILE_BYTES;
constexpr int OFF_U     = 4 * TILE_BYTES;    // X (single fp16)
constexpr int OFF_V     = 5 * TILE_BYTES;    // T (single fp16)
constexpr int SMEM_BYTES = 6 * TILE_BYTES;

// ---------------- helpers ----------------
DI uint32_t smem_u32(const void* p) {
    uint32_t a;
    asm("{ .reg .u64 t; cvta.to.shared.u64 t, %1; cvt.u32.u64 %0, t; }" : "=r"(a) : "l"(p));
    return a;
}

// Byte offset of (row, col[fp16]) in a swizzled 128x128 fp16 tile.
// Row = 256 B = 16 chunks of 16 B; chunk index XORed with (row & 7) so
// 8 consecutive rows hit 8 distinct bank groups (conflict-free ldmatrix).
DI uint32_t toff(int row, int col) {
    return (uint32_t)(row * ROW_BYTES) + ((((col >> 3) ^ (row & 7)) << 4)) +
           ((col & 7) << 1);
}

DI void ldsm4(uint32_t& r0, uint32_t& r1, uint32_t& r2, uint32_t& r3, uint32_t a) {
    asm volatile("ldmatrix.sync.aligned.m8n8.x4.shared.b16 {%0,%1,%2,%3}, [%4];"
                 : "=r"(r0), "=r"(r1), "=r"(r2), "=r"(r3) : "r"(a));
}

DI void mma16816(float* d, const uint32_t* a, uint32_t b0, uint32_t b1) {
    asm volatile(
        "mma.sync.aligned.m16n8k16.row.col.f32.f16.f16.f32 "
        "{%0,%1,%2,%3}, {%4,%5,%6,%7}, {%8,%9}, {%0,%1,%2,%3};"
        : "+f"(d[0]), "+f"(d[1]), "+f"(d[2]), "+f"(d[3])
        : "r"(a[0]), "r"(a[1]), "r"(a[2]), "r"(a[3]), "r"(b0), "r"(b1));
}

DI uint32_t f2h2(float a, float b) {
    __half2 h = __floats2half2_rn(a, b);
    return *reinterpret_cast<uint32_t*>(&h);
}

// Weight split: w = hi + lo, each fp16 (represents w to ~2^-24).
DI void wsplit2(float a, float b, uint32_t& h, uint32_t& l) {
    __half ha = __float2half_rn(a);
    __half hb = __float2half_rn(b);
    __half la = __float2half_rn(a - __half2float(ha));
    __half lb = __float2half_rn(b - __half2float(hb));
    h = (uint32_t)__half_as_ushort(ha) | ((uint32_t)__half_as_ushort(hb) << 16);
    l = (uint32_t)__half_as_ushort(la) | ((uint32_t)__half_as_ushort(lb) << 16);
}

// One-time: load 128x128 fp32 weight, split hi/lo fp16, store swizzled tiles.
DI void cvt_weight(const float* __restrict__ src, char* smem, int off_hi, int off_lo,
                   int tid) {
#pragma unroll
    for (int it = 0; it < 2048 / NT; it++) {
        int g = tid + it * NT;
        int row = g >> 4;
        int col = (g & 15) << 3;
        const float4* p = reinterpret_cast<const float4*>(src + row * DIM + col);
        float4 v0 = p[0];
        float4 v1 = p[1];
        uint4 hi, lo;
        wsplit2(v0.x, v0.y, hi.x, lo.x);
        wsplit2(v0.z, v0.w, hi.y, lo.y);
        wsplit2(v1.x, v1.y, hi.z, lo.z);
        wsplit2(v1.z, v1.w, hi.w, lo.w);
        uint32_t o = toff(row, col);
        *reinterpret_cast<uint4*>(smem + off_hi + o) = hi;
        *reinterpret_cast<uint4*>(smem + off_lo + o) = lo;
    }
}

// Load 128x128 fp32 from gmem, convert to single fp16 swizzled tile.
DI void cvt_x(const float* __restrict__ src, char* smem, int off, int tid) {
#pragma unroll
    for (int it = 0; it < 2048 / NT; it++) {
        int g = tid + it * NT;
        int row = g >> 4;
        int col = (g & 15) << 3;
        const float4* p = reinterpret_cast<const float4*>(src + row * DIM + col);
        float4 v0 = p[0];
        float4 v1 = p[1];
        uint4 h;
        h.x = f2h2(v0.x, v0.y);
        h.y = f2h2(v0.z, v0.w);
        h.z = f2h2(v1.x, v1.y);
        h.w = f2h2(v1.z, v1.w);
        *reinterpret_cast<uint4*>(smem + off + toff(row, col)) = h;
    }
}

// 128x128x128 GEMM, 2 passes (Ah*B + Al*B), warp tile m32 x n32.
DI void gemm2p(float acc[2][4][4], uint32_t a_hi, uint32_t a_lo, uint32_t b_t,
               int m0, int n0, int lane) {
    const int a_row = lane & 15;
    const int a_col = (lane >> 4) << 3;
    const int b_row = (lane & 7) + ((lane >> 4) << 3);
    const int b_col = ((lane >> 3) & 1) << 3;

#pragma unroll
    for (int k = 0; k < 8; k++) {
        const int kb = k << 4;
        uint32_t Ah[2][4], Al[2][4], B[2][4];
#pragma unroll
        for (int mt = 0; mt < 2; mt++) {
            uint32_t o = toff(m0 + mt * 16 + a_row, kb + a_col);
            ldsm4(Ah[mt][0], Ah[mt][1], Ah[mt][2], Ah[mt][3], a_hi + o);
            ldsm4(Al[mt][0], Al[mt][1], Al[mt][2], Al[mt][3], a_lo + o);
        }
#pragma unroll
        for (int p = 0; p < 2; p++) {
            uint32_t o = toff(n0 + p * 16 + b_row, kb + b_col);
            ldsm4(B[p][0], B[p][1], B[p][2], B[p][3], b_t + o);
        }
#pragma unroll
        for (int mt = 0; mt < 2; mt++) {
#pragma unroll
            for (int nt = 0; nt < 4; nt++) {
                const int p = nt >> 1, q = (nt & 1) << 1;
                mma16816(acc[mt][nt], Ah[mt], B[p][q], B[p][q + 1]);
                mma16816(acc[mt][nt], Al[mt], B[p][q], B[p][q + 1]);
            }
        }
    }
}

DI void zero_acc(float acc[2][4][4]) {
#pragma unroll
    for (int mt = 0; mt < 2; mt++)
#pragma unroll
        for (int nt = 0; nt < 4; nt++)
#pragma unroll
            for (int i = 0; i < 4; i++) acc[mt][nt][i] = 0.f;
}

// ---------------- kernel ----------------
// GEMM1: D1[o_b, j] = sum_k Wb[o_b,k] * X[j,k]   (B = X natural row-major)
// GEMM2: D2[o_a, o_b] = sum_j Wa[o_a,j] * T[o_b,j]
// out[n, o_a*128+o_b] = D2 + bias
__global__ void __launch_bounds__(NT, 1)
krone_kernel(const float* __restrict__ x, const float* __restrict__ wa,
             const float* __restrict__ wb, const float* __restrict__ bias,
             float* __restrict__ out, int n_samples) {
    extern __shared__ char smem[];
    const uint32_t sb = smem_u32(smem);
    const int tid = threadIdx.x;
    const int wid = tid >> 5;
    const int lane = tid & 31;
    const int m0 = (wid & 3) * 32;
    const int n0 = (wid >> 2) * 32;

    // One-time: weights (split) + first sample (single) into smem
    cvt_weight(wb, smem, OFF_WB_HI, OFF_WB_LO, tid);
    cvt_weight(wa, smem, OFF_WA_HI, OFF_WA_LO, tid);
    {
        int n0s = blockIdx.x < n_samples ? blockIdx.x : 0;
        cvt_x(x + (size_t)n0s * ROW_FLOATS, smem, OFF_U, tid);
    }
    __syncthreads();

    const int er = lane >> 2;
    const int ec = (lane & 3) << 1;

    float acc[2][4][4];

    for (int n = blockIdx.x; n < n_samples; n += gridDim.x) {
        // ===== phase 1: GEMM1 (reads U, Wb) + storeT (writes V) =====
        zero_acc(acc);
        gemm2p(acc, sb + OFF_WB_HI, sb + OFF_WB_LO, sb + OFF_U, m0, n0, lane);
#pragma unroll
        for (int mt = 0; mt < 2; mt++) {
#pragma unroll
            for (int nt = 0; nt < 4; nt++) {
                const int col = n0 + nt * 8 + ec;
                *reinterpret_cast<uint32_t*>(
                    smem + OFF_V + toff(m0 + mt * 16 + er, col)) =
                    f2h2(acc[mt][nt][0], acc[mt][nt][1]);
                *reinterpret_cast<uint32_t*>(
                    smem + OFF_V + toff(m0 + mt * 16 + er + 8, col)) =
                    f2h2(acc[mt][nt][2], acc[mt][nt][3]);
            }
        }
        __syncthreads();   // T ready; U free (all GEMM1 reads done)

        // ===== phase 2: prefetch next x | GEMM2 | epilogue | cvt-STS =====
        int np = n + gridDim.x;
        if (np >= n_samples) np = n;   // clamp: harmless reload on last iter
        const float* src = x + (size_t)np * ROW_FLOATS;
        float4 pf[8];
#pragma unroll
        for (int it = 0; it < 4; it++) {
            int g = tid + it * NT;
            const float4* p =
                reinterpret_cast<const float4*>(src + (g >> 4) * DIM + ((g & 15) << 3));
            pf[it * 2]     = p[0];
            pf[it * 2 + 1] = p[1];
        }

        zero_acc(acc);
        gemm2p(acc, sb + OFF_WA_HI, sb + OFF_WA_LO, sb + OFF_V, m0, n0, lane);

        float* outn = out + (size_t)n * ROW_FLOATS;
#pragma unroll
        for (int mt = 0; mt < 2; mt++) {
#pragma unroll
            for (int nt = 0; nt < 4; nt++) {
                const int col = n0 + nt * 8 + ec;
                int row = m0 + mt * 16 + er;
                float2 bv = *reinterpret_cast<const float2*>(bias + row * DIM + col);
                float2 o0 = {acc[mt][nt][0] + bv.x, acc[mt][nt][1] + bv.y};
                *reinterpret_cast<float2*>(outn + row * DIM + col) = o0;
                row += 8;
                bv = *reinterpret_cast<const float2*>(bias + row * DIM + col);
                float2 o1 = {acc[mt][nt][2] + bv.x, acc[mt][nt][3] + bv.y};
                *reinterpret_cast<float2*>(outn + row * DIM + col) = o1;
            }
        }

        // store prefetched next sample into U (free since the barrier above)
#pragma unroll
        for (int it = 0; it < 4; it++) {
            int g = tid + it * NT;
            uint4 h;
            h.x = f2h2(pf[it * 2].x,     pf[it * 2].y);
            h.y = f2h2(pf[it * 2].z,     pf[it * 2].w);
            h.z = f2h2(pf[it * 2 + 1].x, pf[it * 2 + 1].y);
            h.w = f2h2(pf[it * 2 + 1].z, pf[it * 2 + 1].w);
            *reinterpret_cast<uint4*>(smem + OFF_U + toff(g >> 4, (g & 15) << 3)) = h;
        }
        __syncthreads();   // next X staged; V reads (GEMM2) all done
    }
}

// ---------------- launcher ----------------
extern "C" void kernel_launch(void* const* d_in, const int* in_sizes, int n_in,
                              void* d_out, int out_size) {
    const float* x    = (const float*)d_in[0];
    const float* wa   = (const float*)d_in[1];
    const float* wb   = (const float*)d_in[2];
    const float* bias = (const float*)d_in[3];
    float* out = (float*)d_out;
    int n_samples = in_sizes[0] / ROW_FLOATS;

    cudaFuncSetAttribute(krone_kernel, cudaFuncAttributeMaxDynamicSharedMemorySize,
                         SMEM_BYTES);
    int grid = n_samples < 148 ? n_samples : 148;
    krone_kernel<<<grid, NT, SMEM_BYTES>>>(x, wa, wb, bias, out, n_samples);
}

// round 8
// speedup vs baseline: 2.2321x; 1.3207x over previous
#include <cuda_runtime.h>
#include <cuda_fp16.h>
#include <cstdint>

#define DI __device__ __forceinline__

// ---------------- constants ----------------
constexpr int DIM = 128;
constexpr int ROW_FLOATS = DIM * DIM;        // 16384 floats per sample
constexpr int ROW_BYTES = DIM * 2;           // 256 B per fp16 tile row
constexpr int TILE_BYTES = DIM * ROW_BYTES;  // 32 KB
constexpr int NT = 512;                      // 16 warps, all compute

// SMEM map
constexpr int OFF_WB   = 0;
constexpr int OFF_WA   = 1 * TILE_BYTES;
constexpr int OFF_U    = 2 * TILE_BYTES;     // X (fp16)
constexpr int OFF_V    = 3 * TILE_BYTES;     // T (fp16)
constexpr int OFF_BIAS = 4 * TILE_BYTES;     // fp32, row stride 132 floats
constexpr int BSTRIDE = 132;                 // 16B-aligned rows, conflict-free
constexpr int SMEM_BYTES = OFF_BIAS + DIM * BSTRIDE * 4;  // 198656 B

// ---------------- helpers ----------------
DI uint32_t smem_u32(const void* p) {
    uint32_t a;
    asm("{ .reg .u64 t; cvta.to.shared.u64 t, %1; cvt.u32.u64 %0, t; }" : "=r"(a) : "l"(p));
    return a;
}

// Byte offset of (row, col[fp16]) in a swizzled 128x128 fp16 tile.
// Row = 256 B = 16 chunks of 16 B; chunk index XORed with (row & 7) so
// 8 consecutive rows hit 8 distinct bank groups (conflict-free ldmatrix).
DI uint32_t toff(int row, int col) {
    return (uint32_t)(row * ROW_BYTES) + ((((col >> 3) ^ (row & 7)) << 4)) +
           ((col & 7) << 1);
}

DI void ldsm4(uint32_t& r0, uint32_t& r1, uint32_t& r2, uint32_t& r3, uint32_t a) {
    asm volatile("ldmatrix.sync.aligned.m8n8.x4.shared.b16 {%0,%1,%2,%3}, [%4];"
                 : "=r"(r0), "=r"(r1), "=r"(r2), "=r"(r3) : "r"(a));
}

DI void mma16816(float* d, const uint32_t* a, uint32_t b0, uint32_t b1) {
    asm volatile(
        "mma.sync.aligned.m16n8k16.row.col.f32.f16.f16.f32 "
        "{%0,%1,%2,%3}, {%4,%5,%6,%7}, {%8,%9}, {%0,%1,%2,%3};"
        : "+f"(d[0]), "+f"(d[1]), "+f"(d[2]), "+f"(d[3])
        : "r"(a[0]), "r"(a[1]), "r"(a[2]), "r"(a[3]), "r"(b0), "r"(b1));
}

DI uint32_t f2h2(float a, float b) {
    __half2 h = __floats2half2_rn(a, b);
    return *reinterpret_cast<uint32_t*>(&h);
}

// Load 128x128 fp32 from gmem, convert to single fp16 swizzled tile.
DI void cvt_x(const float* __restrict__ src, char* smem, int off, int tid) {
#pragma unroll
    for (int it = 0; it < 2048 / NT; it++) {
        int g = tid + it * NT;
        int row = g >> 4;
        int col = (g & 15) << 3;
        const float4* p = reinterpret_cast<const float4*>(src + row * DIM + col);
        float4 v0 = p[0];
        float4 v1 = p[1];
        uint4 h;
        h.x = f2h2(v0.x, v0.y);
        h.y = f2h2(v0.z, v0.w);
        h.z = f2h2(v1.x, v1.y);
        h.w = f2h2(v1.z, v1.w);
        *reinterpret_cast<uint4*>(smem + off + toff(row, col)) = h;
    }
}

// 128x128x128 fp16 GEMM, single pass, warp tile m32 x n32.
DI void gemm1p(float acc[2][4][4], uint32_t a_t, uint32_t b_t,
               int m0, int n0, int lane) {
    const int a_row = lane & 15;
    const int a_col = (lane >> 4) << 3;
    const int b_row = (lane & 7) + ((lane >> 4) << 3);
    const int b_col = ((lane >> 3) & 1) << 3;

#pragma unroll
    for (int k = 0; k < 8; k++) {
        const int kb = k << 4;
        uint32_t A[2][4], B[2][4];
#pragma unroll
        for (int mt = 0; mt < 2; mt++) {
            uint32_t o = toff(m0 + mt * 16 + a_row, kb + a_col);
            ldsm4(A[mt][0], A[mt][1], A[mt][2], A[mt][3], a_t + o);
        }
#pragma unroll
        for (int p = 0; p < 2; p++) {
            uint32_t o = toff(n0 + p * 16 + b_row, kb + b_col);
            ldsm4(B[p][0], B[p][1], B[p][2], B[p][3], b_t + o);
        }
#pragma unroll
        for (int mt = 0; mt < 2; mt++) {
#pragma unroll
            for (int nt = 0; nt < 4; nt++) {
                const int p = nt >> 1, q = (nt & 1) << 1;
                mma16816(acc[mt][nt], A[mt], B[p][q], B[p][q + 1]);
            }
        }
    }
}

DI void zero_acc(float acc[2][4][4]) {
#pragma unroll
    for (int mt = 0; mt < 2; mt++)
#pragma unroll
        for (int nt = 0; nt < 4; nt++)
#pragma unroll
            for (int i = 0; i < 4; i++) acc[mt][nt][i] = 0.f;
}

// ---------------- kernel ----------------
// GEMM1: D1[o_b, j] = sum_k Wb[o_b,k] * X[j,k]   (B = X natural row-major)
// GEMM2: D2[o_a, o_b] = sum_j Wa[o_a,j] * T[o_b,j]
// out[n, o_a*128+o_b] = D2 + bias
__global__ void __launch_bounds__(NT, 1)
krone_kernel(const float* __restrict__ x, const float* __restrict__ wa,
             const float* __restrict__ wb, const float* __restrict__ bias,
             float* __restrict__ out, int n_samples) {
    extern __shared__ char smem[];
    const uint32_t sb = smem_u32(smem);
    const int tid = threadIdx.x;
    const int wid = tid >> 5;
    const int lane = tid & 31;
    const int m0 = (wid & 3) * 32;
    const int n0 = (wid >> 2) * 32;

    // One-time: weights (single fp16), first sample, bias -> smem
    cvt_x(wb, smem, OFF_WB, tid);
    cvt_x(wa, smem, OFF_WA, tid);
    {
        int n0s = blockIdx.x < n_samples ? blockIdx.x : 0;
        cvt_x(x + (size_t)n0s * ROW_FLOATS, smem, OFF_U, tid);
    }
    {
        float* bst = reinterpret_cast<float*>(smem + OFF_BIAS);
#pragma unroll
        for (int it = 0; it < 4096 / NT; it++) {
            int g = tid + it * NT;                    // float4 index
            float4 v = reinterpret_cast<const float4*>(bias)[g];
            int row = g >> 5, c4 = (g & 31) << 2;
            *reinterpret_cast<float4*>(bst + row * BSTRIDE + c4) = v;
        }
    }
    __syncthreads();

    const int er = lane >> 2;
    const int ec = (lane & 3) << 1;
    const float* bst = reinterpret_cast<const float*>(smem + OFF_BIAS);

    float acc[2][4][4];

    for (int n = blockIdx.x; n < n_samples; n += gridDim.x) {
        // ===== phase 1: GEMM1 (reads U, Wb) + storeT (writes V) =====
        zero_acc(acc);
        gemm1p(acc, sb + OFF_WB, sb + OFF_U, m0, n0, lane);
#pragma unroll
        for (int mt = 0; mt < 2; mt++) {
#pragma unroll
            for (int nt = 0; nt < 4; nt++) {
                const int col = n0 + nt * 8 + ec;
                *reinterpret_cast<uint32_t*>(
                    smem + OFF_V + toff(m0 + mt * 16 + er, col)) =
                    f2h2(acc[mt][nt][0], acc[mt][nt][1]);
                *reinterpret_cast<uint32_t*>(
                    smem + OFF_V + toff(m0 + mt * 16 + er + 8, col)) =
                    f2h2(acc[mt][nt][2], acc[mt][nt][3]);
            }
        }
        __syncthreads();   // T ready; U free (all GEMM1 reads done)

        // ===== phase 2: prefetch next x | GEMM2 | epilogue | cvt-STS =====
        int np = n + gridDim.x;
        if (np >= n_samples) np = n;   // clamp: harmless reload on last iter
        const float* src = x + (size_t)np * ROW_FLOATS;
        float4 pf[8];
#pragma unroll
        for (int it = 0; it < 4; it++) {
            int g = tid + it * NT;
            const float4* p =
                reinterpret_cast<const float4*>(src + (g >> 4) * DIM + ((g & 15) << 3));
            pf[it * 2]     = p[0];
            pf[it * 2 + 1] = p[1];
        }

        zero_acc(acc);
        gemm1p(acc, sb + OFF_WA, sb + OFF_V, m0, n0, lane);

        float* outn = out + (size_t)n * ROW_FLOATS;
#pragma unroll
        for (int mt = 0; mt < 2; mt++) {
#pragma unroll
            for (int nt = 0; nt < 4; nt++) {
                const int col = n0 + nt * 8 + ec;
                int row = m0 + mt * 16 + er;
                float2 bv = *reinterpret_cast<const float2*>(bst + row * BSTRIDE + col);
                float2 o0 = {acc[mt][nt][0] + bv.x, acc[mt][nt][1] + bv.y};
                *reinterpret_cast<float2*>(outn + row * DIM + col) = o0;
                row += 8;
                bv = *reinterpret_cast<const float2*>(bst + row * BSTRIDE + col);
                float2 o1 = {acc[mt][nt][2] + bv.x, acc[mt][nt][3] + bv.y};
                *reinterpret_cast<float2*>(outn + row * DIM + col) = o1;
            }
        }

        // store prefetched next sample into U (free since the barrier above)
#pragma unroll
        for (int it = 0; it < 4; it++) {
            int g = tid + it * NT;
            uint4 h;
            h.x = f2h2(pf[it * 2].x,     pf[it * 2].y);
            h.y = f2h2(pf[it * 2].z,     pf[it * 2].w);
            h.z = f2h2(pf[it * 2 + 1].x, pf[it * 2 + 1].y);
            h.w = f2h2(pf[it * 2 + 1].z, pf[it * 2 + 1].w);
            *reinterpret_cast<uint4*>(smem + OFF_U + toff(g >> 4, (g & 15) << 3)) = h;
        }
        __syncthreads();   // next X staged; V reads (GEMM2) all done
    }
}

// ---------------- launcher ----------------
extern "C" void kernel_launch(void* const* d_in, const int* in_sizes, int n_in,
                              void* d_out, int out_size) {
    const float* x    = (const float*)d_in[0];
    const float* wa   = (const float*)d_in[1];
    const float* wb   = (const float*)d_in[2];
    const float* bias = (const float*)d_in[3];
    float* out = (float*)d_out;
    int n_samples = in_sizes[0] / ROW_FLOATS;

    cudaFuncSetAttribute(krone_kernel, cudaFuncAttributeMaxDynamicSharedMemorySize,
                         SMEM_BYTES);
    int grid = n_samples < 148 ? n_samples : 148;
    krone_kernel<<<grid, NT, SMEM_BYTES>>>(x, wa, wb, bias, out, n_samples);
}

// round 10
// speedup vs baseline: 2.2334x; 1.0006x over previous
#include <cuda_runtime.h>
#include <cuda_fp16.h>
#include <cstdint>

#define DI __device__ __forceinline__

// ---------------- constants ----------------
constexpr int DIM = 128;
constexpr int ROW_FLOATS = DIM * DIM;        // 16384 floats per sample
constexpr int ROW_BYTES = DIM * 2;           // 256 B per fp16 tile row
constexpr int TILE_BYTES = DIM * ROW_BYTES;  // 32 KB
constexpr int NT = 256;                      // 8 warps; 2 CTAs per SM

// SMEM map: 3 tiles = 96 KB per CTA (2 CTAs fit in 227 KB)
constexpr int OFF_WB = 0;
constexpr int OFF_WA = 1 * TILE_BYTES;
constexpr int OFF_U  = 2 * TILE_BYTES;       // X -> T -> next X (aliased)
constexpr int SMEM_BYTES = 3 * TILE_BYTES;   // 98304 B

// ---------------- helpers ----------------
DI uint32_t smem_u32(const void* p) {
    uint32_t a;
    asm("{ .reg .u64 t; cvta.to.shared.u64 t, %1; cvt.u32.u64 %0, t; }" : "=r"(a) : "l"(p));
    return a;
}

// Byte offset of (row, col[fp16]) in a swizzled 128x128 fp16 tile.
// Row = 256 B = 16 chunks of 16 B; chunk index XORed with (row & 7) so
// 8 consecutive rows hit 8 distinct bank groups (conflict-free ldmatrix).
DI uint32_t toff(int row, int col) {
    return (uint32_t)(row * ROW_BYTES) + ((((col >> 3) ^ (row & 7)) << 4)) +
           ((col & 7) << 1);
}

DI void ldsm4(uint32_t& r0, uint32_t& r1, uint32_t& r2, uint32_t& r3, uint32_t a) {
    asm volatile("ldmatrix.sync.aligned.m8n8.x4.shared.b16 {%0,%1,%2,%3}, [%4];"
                 : "=r"(r0), "=r"(r1), "=r"(r2), "=r"(r3) : "r"(a));
}

DI void mma16816(float* d, const uint32_t* a, uint32_t b0, uint32_t b1) {
    asm volatile(
        "mma.sync.aligned.m16n8k16.row.col.f32.f16.f16.f32 "
        "{%0,%1,%2,%3}, {%4,%5,%6,%7}, {%8,%9}, {%0,%1,%2,%3};"
        : "+f"(d[0]), "+f"(d[1]), "+f"(d[2]), "+f"(d[3])
        : "r"(a[0]), "r"(a[1]), "r"(a[2]), "r"(a[3]), "r"(b0), "r"(b1));
}

DI uint32_t f2h2(float a, float b) {
    __half2 h = __floats2half2_rn(a, b);
    return *reinterpret_cast<uint32_t*>(&h);
}

// Load 128x128 fp32 from gmem, convert to single fp16 swizzled tile.
DI void cvt_x(const float* __restrict__ src, char* smem, int off, int tid) {
#pragma unroll
    for (int it = 0; it < 2048 / NT; it++) {
        int g = tid + it * NT;
        int row = g >> 4;
        int col = (g & 15) << 3;
        const float4* p = reinterpret_cast<const float4*>(src + row * DIM + col);
        float4 v0 = p[0];
        float4 v1 = p[1];
        uint4 h;
        h.x = f2h2(v0.x, v0.y);
        h.y = f2h2(v0.z, v0.w);
        h.z = f2h2(v1.x, v1.y);
        h.w = f2h2(v1.z, v1.w);
        *reinterpret_cast<uint4*>(smem + off + toff(row, col)) = h;
    }
}

// 128x128x128 fp16 GEMM, warp tile m32 x n64.
DI void gemm1p(float acc[2][8][4], uint32_t a_t, uint32_t b_t,
               int m0, int n0, int lane) {
    const int a_row = lane & 15;
    const int a_col = (lane >> 4) << 3;
    const int b_row = (lane & 7) + ((lane >> 4) << 3);
    const int b_col = ((lane >> 3) & 1) << 3;

#pragma unroll
    for (int k = 0; k < 8; k++) {
        const int kb = k << 4;
        uint32_t A[2][4];
#pragma unroll
        for (int mt = 0; mt < 2; mt++) {
            uint32_t o = toff(m0 + mt * 16 + a_row, kb + a_col);
            ldsm4(A[mt][0], A[mt][1], A[mt][2], A[mt][3], a_t + o);
        }
#pragma unroll
        for (int p = 0; p < 4; p++) {
            uint32_t B[4];
            uint32_t o = toff(n0 + p * 16 + b_row, kb + b_col);
            ldsm4(B[0], B[1], B[2], B[3], b_t + o);
#pragma unroll
            for (int mt = 0; mt < 2; mt++) {
#pragma unroll
                for (int qn = 0; qn < 2; qn++) {
                    mma16816(acc[mt][p * 2 + qn], A[mt], B[qn * 2], B[qn * 2 + 1]);
                }
            }
        }
    }
}

DI void zero_acc(float acc[2][8][4]) {
#pragma unroll
    for (int mt = 0; mt < 2; mt++)
#pragma unroll
        for (int nt = 0; nt < 8; nt++)
#pragma unroll
            for (int i = 0; i < 4; i++) acc[mt][nt][i] = 0.f;
}

// ---------------- kernel ----------------
// GEMM1: D1[o_b, j] = sum_k Wb[o_b,k] * X[j,k]   (B = X natural row-major)
// GEMM2: D2[o_a, o_b] = sum_j Wa[o_a,j] * T[o_b,j]
// out[n, o_a*128+o_b] = D2 + bias
__global__ void __launch_bounds__(NT, 2)
krone_kernel(const float* __restrict__ x, const float* __restrict__ wa,
             const float* __restrict__ wb, const float* __restrict__ bias,
             float* __restrict__ out, int n_samples) {
    extern __shared__ char smem[];
    const uint32_t sb = smem_u32(smem);
    const int tid = threadIdx.x;
    const int wid = tid >> 5;
    const int lane = tid & 31;
    const int m0 = (wid & 3) * 32;     // output rows
    const int n0 = (wid >> 2) * 64;    // output cols

    // One-time: weights (fp16) + first sample -> smem
    cvt_x(wb, smem, OFF_WB, tid);
    cvt_x(wa, smem, OFF_WA, tid);
    {
        int n0s = blockIdx.x < n_samples ? blockIdx.x : 0;
        cvt_x(x + (size_t)n0s * ROW_FLOATS, smem, OFF_U, tid);
    }
    __syncthreads();

    const int er = lane >> 2;
    const int ec = (lane & 3) << 1;

    float acc[2][8][4];

    for (int n = blockIdx.x; n < n_samples; n += gridDim.x) {
        // ===== GEMM1: reads U (X), Wb =====
        zero_acc(acc);
        gemm1p(acc, sb + OFF_WB, sb + OFF_U, m0, n0, lane);
        __syncthreads();   // all warps done reading U

        // ===== storeT: T[o_b][j] overwrites U =====
#pragma unroll
        for (int mt = 0; mt < 2; mt++) {
#pragma unroll
            for (int nt = 0; nt < 8; nt++) {
                const int col = n0 + nt * 8 + ec;
                *reinterpret_cast<uint32_t*>(
                    smem + OFF_U + toff(m0 + mt * 16 + er, col)) =
                    f2h2(acc[mt][nt][0], acc[mt][nt][1]);
                *reinterpret_cast<uint32_t*>(
                    smem + OFF_U + toff(m0 + mt * 16 + er + 8, col)) =
                    f2h2(acc[mt][nt][2], acc[mt][nt][3]);
            }
        }
        __syncthreads();   // T ready

        // ===== GEMM2: reads U (T), Wa; epilogue to gmem =====
        zero_acc(acc);
        gemm1p(acc, sb + OFF_WA, sb + OFF_U, m0, n0, lane);

        float* outn = out + (size_t)n * ROW_FLOATS;
#pragma unroll
        for (int mt = 0; mt < 2; mt++) {
#pragma unroll
            for (int nt = 0; nt < 8; nt++) {
                const int col = n0 + nt * 8 + ec;
                int row = m0 + mt * 16 + er;
                float2 bv = *reinterpret_cast<const float2*>(bias + row * DIM + col);
                float2 o0 = {acc[mt][nt][0] + bv.x, acc[mt][nt][1] + bv.y};
                *reinterpret_cast<float2*>(outn + row * DIM + col) = o0;
                row += 8;
                bv = *reinterpret_cast<const float2*>(bias + row * DIM + col);
                float2 o1 = {acc[mt][nt][2] + bv.x, acc[mt][nt][3] + bv.y};
                *reinterpret_cast<float2*>(outn + row * DIM + col) = o1;
            }
        }
        __syncthreads();   // all warps done reading U (T)

        // ===== stage next sample's X into U =====
        int np = n + gridDim.x;
        if (np >= n_samples) np = n;   // clamp: harmless reload on last iter
        cvt_x(x + (size_t)np * ROW_FLOATS, smem, OFF_U, tid);
        __syncthreads();   // next X ready
    }
}

// ---------------- launcher ----------------
extern "C" void kernel_launch(void* const* d_in, const int* in_sizes, int n_in,
                              void* d_out, int out_size) {
    const float* x    = (const float*)d_in[0];
    const float* wa   = (const float*)d_in[1];
    const float* wb   = (const float*)d_in[2];
    const float* bias = (const float*)d_in[3];
    float* out = (float*)d_out;
    int n_samples = in_sizes[0] / ROW_FLOATS;

    cudaFuncSetAttribute(krone_kernel, cudaFuncAttributeMaxDynamicSharedMemorySize,
                         SMEM_BYTES);
    int grid = n_samples < 296 ? n_samples : 296;
    krone_kernel<<<grid, NT, SMEM_BYTES>>>(x, wa, wb, bias, out, n_samples);
}

// round 14
// speedup vs baseline: 2.2536x; 1.0090x over previous
#include <cuda_runtime.h>
#include <cuda_fp16.h>
#include <cstdint>

#define DI __device__ __forceinline__

// ---------------- constants ----------------
constexpr int DIM = 128;
constexpr int ROW_FLOATS = DIM * DIM;        // 16384 floats per sample
constexpr int ROW_BYTES = DIM * 2;           // 256 B per fp16 tile row
constexpr int TILE_BYTES = DIM * ROW_BYTES;  // 32 KB
constexpr int NT = 256;                      // 8 warps; 2 CTAs per SM
constexpr int CHUNKS_PT = 2048 / NT;         // 8 16B-chunks per thread per tile

// SMEM map: 3 tiles = 96 KB per CTA (2 CTAs/SM)
constexpr int OFF_WB = 0;
constexpr int OFF_WA = 1 * TILE_BYTES;
constexpr int OFF_U  = 2 * TILE_BYTES;       // X -> T -> next X (aliased)
constexpr int SMEM_BYTES = 3 * TILE_BYTES;   // 98304 B

// ---------------- helpers ----------------
DI uint32_t smem_u32(const void* p) {
    uint32_t a;
    asm("{ .reg .u64 t; cvta.to.shared.u64 t, %1; cvt.u32.u64 %0, t; }" : "=r"(a) : "l"(p));
    return a;
}

// Byte offset of (row, col[fp16]) in a swizzled 128x128 fp16 tile.
// Row = 256 B = 16 chunks of 16 B; chunk index XORed with (row & 7) so
// 8 consecutive rows hit 8 distinct bank groups (conflict-free ldmatrix).
DI uint32_t toff(int row, int col) {
    return (uint32_t)(row * ROW_BYTES) + ((((col >> 3) ^ (row & 7)) << 4)) +
           ((col & 7) << 1);
}

DI void ldsm4(uint32_t& r0, uint32_t& r1, uint32_t& r2, uint32_t& r3, uint32_t a) {
    asm volatile("ldmatrix.sync.aligned.m8n8.x4.shared.b16 {%0,%1,%2,%3}, [%4];"
                 : "=r"(r0), "=r"(r1), "=r"(r2), "=r"(r3) : "r"(a));
}

DI void mma16816(float* d, const uint32_t* a, uint32_t b0, uint32_t b1) {
    asm volatile(
        "mma.sync.aligned.m16n8k16.row.col.f32.f16.f16.f32 "
        "{%0,%1,%2,%3}, {%4,%5,%6,%7}, {%8,%9}, {%0,%1,%2,%3};"
        : "+f"(d[0]), "+f"(d[1]), "+f"(d[2]), "+f"(d[3])
        : "r"(a[0]), "r"(a[1]), "r"(a[2]), "r"(a[3]), "r"(b0), "r"(b1));
}

DI uint32_t f2h2(float a, float b) {
    __half2 h = __floats2half2_rn(a, b);
    return *reinterpret_cast<uint32_t*>(&h);
}

// Load one 16B fp16 chunk's worth of fp32 (32 B) and convert.
DI uint4 load_cvt_chunk(const float* __restrict__ src, int g) {
    const float4* p =
        reinterpret_cast<const float4*>(src + (g >> 4) * DIM + ((g & 15) << 3));
    float4 v0 = p[0];
    float4 v1 = p[1];
    uint4 h;
    h.x = f2h2(v0.x, v0.y);
    h.y = f2h2(v0.z, v0.w);
    h.z = f2h2(v1.x, v1.y);
    h.w = f2h2(v1.z, v1.w);
    return h;
}

// Load 128x128 fp32 from gmem, convert to single fp16 swizzled tile.
DI void cvt_x(const float* __restrict__ src, char* smem, int off, int tid) {
#pragma unroll
    for (int it = 0; it < CHUNKS_PT; it++) {
        int g = tid + it * NT;
        *reinterpret_cast<uint4*>(smem + off + toff(g >> 4, (g & 15) << 3)) =
            load_cvt_chunk(src, g);
    }
}

// 128x128x128 fp16 GEMM, warp tile m32 x n64.
DI void gemm1p(float acc[2][8][4], uint32_t a_t, uint32_t b_t,
               int m0, int n0, int lane) {
    const int a_row = lane & 15;
    const int a_col = (lane >> 4) << 3;
    const int b_row = (lane & 7) + ((lane >> 4) << 3);
    const int b_col = ((lane >> 3) & 1) << 3;

#pragma unroll
    for (int k = 0; k < 8; k++) {
        const int kb = k << 4;
        uint32_t A[2][4];
#pragma unroll
        for (int mt = 0; mt < 2; mt++) {
            uint32_t o = toff(m0 + mt * 16 + a_row, kb + a_col);
            ldsm4(A[mt][0], A[mt][1], A[mt][2], A[mt][3], a_t + o);
        }
#pragma unroll
        for (int p = 0; p < 4; p++) {
            uint32_t B[4];
            uint32_t o = toff(n0 + p * 16 + b_row, kb + b_col);
            ldsm4(B[0], B[1], B[2], B[3], b_t + o);
#pragma unroll
            for (int mt = 0; mt < 2; mt++) {
#pragma unroll
                for (int qn = 0; qn < 2; qn++) {
                    mma16816(acc[mt][p * 2 + qn], A[mt], B[qn * 2], B[qn * 2 + 1]);
                }
            }
        }
    }
}

DI void zero_acc(float acc[2][8][4]) {
#pragma unroll
    for (int mt = 0; mt < 2; mt++)
#pragma unroll
        for (int nt = 0; nt < 8; nt++)
#pragma unroll
            for (int i = 0; i < 4; i++) acc[mt][nt][i] = 0.f;
}

// ---------------- kernel ----------------
// GEMM1: D1[o_b, j] = sum_k Wb[o_b,k] * X[j,k]   (B = X natural row-major)
// GEMM2: D2[o_a, o_b] = sum_j Wa[o_a,j] * T[o_b,j]
// out[n, o_a*128+o_b] = D2 + bias  (bias folded into GEMM2 acc init)
__global__ void __launch_bounds__(NT, 2)
krone_kernel(const float* __restrict__ x, const float* __restrict__ wa,
             const float* __restrict__ wb, const float* __restrict__ bias,
             float* __restrict__ out, int n_samples) {
    extern __shared__ char smem[];
    const uint32_t sb = smem_u32(smem);
    const int tid = threadIdx.x;
    const int wid = tid >> 5;
    const int lane = tid & 31;
    const int m0 = (wid & 3) * 32;     // output rows
    const int n0 = (wid >> 2) * 64;    // output cols

    // One-time: weights (fp16) + first sample -> smem
    cvt_x(wb, smem, OFF_WB, tid);
    cvt_x(wa, smem, OFF_WA, tid);
    {
        int n0s = blockIdx.x < n_samples ? blockIdx.x : 0;
        cvt_x(x + (size_t)n0s * ROW_FLOATS, smem, OFF_U, tid);
    }
    __syncthreads();

    const int er = lane >> 2;
    const int ec = (lane & 3) << 1;

    float acc[2][8][4];
    uint4 pfh[CHUNKS_PT];              // next sample, fp16-converted (32 regs)

    for (int n = blockIdx.x; n < n_samples; n += gridDim.x) {
        // ===== GEMM1: reads U (X), Wb =====
        zero_acc(acc);
        gemm1p(acc, sb + OFF_WB, sb + OFF_U, m0, n0, lane);
        __syncthreads();   // all warps done reading U

        // ===== prefetch + convert next sample's x (FULL tile: 8 chunks/thread)
        int np = n + gridDim.x;
        if (np >= n_samples) np = n;   // clamp: harmless reload on last iter
        const float* src = x + (size_t)np * ROW_FLOATS;
#pragma unroll
        for (int it = 0; it < CHUNKS_PT; it++)
            pfh[it] = load_cvt_chunk(src, tid + it * NT);

        // ===== storeT: T[o_b][j] overwrites U (scalar STS, known-good) =====
#pragma unroll
        for (int mt = 0; mt < 2; mt++) {
#pragma unroll
            for (int nt = 0; nt < 8; nt++) {
                const int col = n0 + nt * 8 + ec;
                *reinterpret_cast<uint32_t*>(
                    smem + OFF_U + toff(m0 + mt * 16 + er, col)) =
                    f2h2(acc[mt][nt][0], acc[mt][nt][1]);
                *reinterpret_cast<uint32_t*>(
                    smem + OFF_U + toff(m0 + mt * 16 + er + 8, col)) =
                    f2h2(acc[mt][nt][2], acc[mt][nt][3]);
            }
        }
        __syncthreads();   // T ready

        // ===== GEMM2: acc init = bias; reads U (T), Wa =====
#pragma unroll
        for (int mt = 0; mt < 2; mt++) {
#pragma unroll
            for (int nt = 0; nt < 8; nt++) {
                const int col = n0 + nt * 8 + ec;
                const int row = m0 + mt * 16 + er;
                float2 b0 = *reinterpret_cast<const float2*>(bias + row * DIM + col);
                float2 b1 = *reinterpret_cast<const float2*>(bias + (row + 8) * DIM + col);
                acc[mt][nt][0] = b0.x;
                acc[mt][nt][1] = b0.y;
                acc[mt][nt][2] = b1.x;
                acc[mt][nt][3] = b1.y;
            }
        }
        gemm1p(acc, sb + OFF_WA, sb + OFF_U, m0, n0, lane);

        // ===== epilogue: pure STG =====
        float* outn = out + (size_t)n * ROW_FLOATS;
#pragma unroll
        for (int mt = 0; mt < 2; mt++) {
#pragma unroll
            for (int nt = 0; nt < 8; nt++) {
                const int col = n0 + nt * 8 + ec;
                const int row = m0 + mt * 16 + er;
                *reinterpret_cast<float2*>(outn + row * DIM + col) =
                    make_float2(acc[mt][nt][0], acc[mt][nt][1]);
                *reinterpret_cast<float2*>(outn + (row + 8) * DIM + col) =
                    make_float2(acc[mt][nt][2], acc[mt][nt][3]);
            }
        }
        __syncthreads();   // all warps done reading U (T)

        // ===== stage prefetched next X into U (pure STS, full tile) =====
#pragma unroll
        for (int it = 0; it < CHUNKS_PT; it++) {
            int g = tid + it * NT;
            *reinterpret_cast<uint4*>(smem + OFF_U + toff(g >> 4, (g & 15) << 3)) =
                pfh[it];
        }
        __syncthreads();   // next X ready
    }
}

// ---------------- launcher ----------------
extern "C" void kernel_launch(void* const* d_in, const int* in_sizes, int n_in,
                              void* d_out, int out_size) {
    const float* x    = (const float*)d_in[0];
    const float* wa   = (const float*)d_in[1];
    const float* wb   = (const float*)d_in[2];
    const float* bias = (const float*)d_in[3];
    float* out = (float*)d_out;
    int n_samples = in_sizes[0] / ROW_FLOATS;

    cudaFuncSetAttribute(krone_kernel, cudaFuncAttributeMaxDynamicSharedMemorySize,
                         SMEM_BYTES);
    int grid = n_samples < 296 ? n_samples : 296;
    krone_kernel<<<grid, NT, SMEM_BYTES>>>(x, wa, wb, bias, out, n_samples);
}